// round 3
// baseline (speedup 1.0000x reference)
#include <cuda_runtime.h>
#include <mma.h>

using namespace nvcuda;

#define NRW 65536
#define HD  256

// ---------------- static device buffers (zero-initialized at module load) ----
__device__ __align__(256) float g_Xp[NRW * 32];            // padded input, cols 20..31 stay 0
__device__ __align__(256) float g_Wih0[1024 * 32];         // padded W_ih_00, cols 20..31 stay 0
__device__ __align__(256) float g_bias[4][1024];           // b_ih + b_hh per layer
__device__ __align__(256) float g_Ybuf[3][(size_t)NRW * HD];
__device__ unsigned g_barCount;
__device__ volatile unsigned g_barGen;

typedef wmma::fragment<wmma::matrix_a, 16, 16, 8, wmma::precision::tf32, wmma::row_major> FragA;
typedef wmma::fragment<wmma::matrix_b, 16, 16, 8, wmma::precision::tf32, wmma::col_major> FragB;
typedef wmma::fragment<wmma::accumulator, 16, 16, 8, float> FragC;

__device__ __forceinline__ float sigf(float x) { return 1.0f / (1.0f + __expf(-x)); }

// 3xTF32 K-loop: acc += A(16xK, row-major, lda) * B(Kx16 as col-major W rows, ldb)
__device__ __forceinline__ void kloop3(FragC& acc, const float* __restrict__ A, int lda,
                                       const float* __restrict__ B, int ldb, int K) {
    for (int k = 0; k < K; k += 8) {
        FragA ah, al;
        FragB bh, bl;
        wmma::load_matrix_sync(ah, A + k, lda);
        wmma::load_matrix_sync(bh, B + k, ldb);
#pragma unroll
        for (int i = 0; i < ah.num_elements; i++) {
            float v = ah.x[i];
            float h = wmma::__float_to_tf32(v);
            al.x[i] = wmma::__float_to_tf32(v - h);
            ah.x[i] = h;
        }
#pragma unroll
        for (int i = 0; i < bh.num_elements; i++) {
            float v = bh.x[i];
            float h = wmma::__float_to_tf32(v);
            bl.x[i] = wmma::__float_to_tf32(v - h);
            bh.x[i] = h;
        }
        wmma::mma_sync(acc, ah, bh, acc);
        wmma::mma_sync(acc, ah, bl, acc);
        wmma::mma_sync(acc, al, bh, acc);
    }
}

// ---------------- prep: pad X / W_ih_00, combine biases ----------------------
__global__ void k_prep(const float* __restrict__ x, const float* __restrict__ wih0,
                       const float* __restrict__ bi0, const float* __restrict__ bh0,
                       const float* __restrict__ bi1, const float* __restrict__ bh1,
                       const float* __restrict__ bi2, const float* __restrict__ bh2,
                       const float* __restrict__ bi3, const float* __restrict__ bh3) {
    int tid = blockIdx.x * blockDim.x + threadIdx.x;
    int nt = gridDim.x * blockDim.x;
    for (int i = tid; i < NRW * 20; i += nt)
        g_Xp[(size_t)(i / 20) * 32 + (i % 20)] = x[i];
    for (int i = tid; i < 1024 * 20; i += nt)
        g_Wih0[(i / 20) * 32 + (i % 20)] = wih0[i];
    for (int i = tid; i < 1024; i += nt) {
        g_bias[0][i] = bi0[i] + bh0[i];
        g_bias[1][i] = bi1[i] + bh1[i];
        g_bias[2][i] = bi2[i] + bh2[i];
        g_bias[3][i] = bi3[i] + bh3[i];
    }
}

// ---------------- grid-wide barrier (all blocks co-resident) -----------------
__device__ __forceinline__ void gridbar() {
    __syncthreads();
    if (threadIdx.x == 0) {
        __threadfence();
        unsigned g = g_barGen;
        unsigned t = atomicAdd(&g_barCount, 1u);
        if (t == gridDim.x - 1u) {
            g_barCount = 0u;
            __threadfence();
            g_barGen = g + 1u;
        } else {
            while (g_barGen == g) __nanosleep(32);
        }
        __threadfence();
    }
    __syncthreads();
}

// ---------------- persistent LSTM layer --------------------------------------
// Tile = TM rows x TH hidden units (4*TH gate columns). TPB tiles per block.
// c state lives in registers for the whole layer.
template <int STEPS, int BEFF, int KIN, int TM, int TH, int TPB>
__global__ void __launch_bounds__(256, 1)
lstm_k(const float* __restrict__ X, const float* __restrict__ Wih,
       const float* __restrict__ Whh, const float* __restrict__ bias,
       float* __restrict__ Y) {
    constexpr int nM = TM / 16;
    constexpr int nHC = 256 / TH;          // hidden-slice chunks
    constexpr int nRow = BEFF / TM;
    constexpr int GCOLS = 4 * TH;
    constexpr int nN = GCOLS / 16;
    constexpr int NS = nM * nN;            // 16x16 subtiles per tile
    constexpr int CPT = (TM * TH) / 256;   // c elems per thread per tile

    __shared__ float sg[TM][GCOLS];

    const int warp = threadIdx.x >> 5;

    float c[TPB][CPT];
#pragma unroll
    for (int tp = 0; tp < TPB; tp++)
#pragma unroll
        for (int q = 0; q < CPT; q++) c[tp][q] = 0.0f;

    for (int t = 0; t < STEPS; t++) {
        if (t) gridbar();
        const size_t rowbase = (size_t)t * BEFF;

#pragma unroll
        for (int tp = 0; tp < TPB; tp++) {
            const int tile = blockIdx.x + tp * gridDim.x;
            const int m0 = (tile / nHC) * TM;
            const int j0 = (tile % nHC) * TH;

            // ---- GEMM: gates tile into smem ----
            for (int st = warp; st < NS; st += 8) {
                const int mi = st / nN;
                const int ni = st % nN;
                const int gate = ni / (TH / 16);
                const int hoff = (ni % (TH / 16)) * 16;
                FragC acc;
                wmma::fill_fragment(acc, 0.0f);

                // input projection: x_t @ W_ih^T
                kloop3(acc, X + (rowbase + m0 + mi * 16) * KIN, KIN,
                       Wih + (size_t)(gate * 256 + j0 + hoff) * KIN, KIN, KIN);
                // recurrent: h_{t-1} @ W_hh^T (h_{-1} = 0)
                if (t) {
                    kloop3(acc, Y + (rowbase - BEFF + m0 + mi * 16) * HD, HD,
                           Whh + (size_t)(gate * 256 + j0 + hoff) * HD, HD, HD);
                }
                wmma::store_matrix_sync(&sg[mi * 16][ni * 16], acc, GCOLS,
                                        wmma::mem_row_major);
            }
            __syncthreads();

            // ---- LSTM elementwise; c in registers ----
            for (int e = threadIdx.x, q = 0; e < TM * TH; e += 256, q++) {
                const int r = e / TH;
                const int h = e % TH;
                const float iv = sg[r][0 * TH + h] + bias[0 * 256 + j0 + h];
                const float fv = sg[r][1 * TH + h] + bias[1 * 256 + j0 + h];
                const float gv = sg[r][2 * TH + h] + bias[2 * 256 + j0 + h];
                const float ov = sg[r][3 * TH + h] + bias[3 * 256 + j0 + h];
                const float cn = sigf(fv) * c[tp][q] + sigf(iv) * tanhf(gv);
                c[tp][q] = cn;
                Y[(rowbase + m0 + r) * HD + j0 + h] = sigf(ov) * tanhf(cn);
            }
            __syncthreads();
        }
    }
}

// ---------------- head: out = tanh((Y2+Y1) @ mlp_w^T + b) @ ad_w^T + ad_b ----
__global__ void __launch_bounds__(256, 2)
head_k(const float* __restrict__ Y2, const float* __restrict__ Y1,
       const float* __restrict__ mlpw, const float* __restrict__ mlpb,
       const float* __restrict__ adw, const float* __restrict__ adb,
       float* __restrict__ out) {
    __shared__ float sx[16][256];
    __shared__ float sh[16][256];
    __shared__ float so[16][48];

    const int warp = threadIdx.x >> 5;
    const size_t m0 = (size_t)blockIdx.x * 16;

    // stage x4 = Y2 + Y1
    for (int e = threadIdx.x; e < 16 * 256; e += 256) {
        const size_t gi = m0 * 256 + e;
        sx[e / 256][e % 256] = Y2[gi] + Y1[gi];
    }
    __syncthreads();

    // GEMM1: 16x256, K=256
    for (int st = warp; st < 16; st += 8) {
        FragC acc;
        wmma::fill_fragment(acc, 0.0f);
        kloop3(acc, &sx[0][0], 256, mlpw + (size_t)(st * 16) * 256, 256, 256);
        wmma::store_matrix_sync(&sh[0][st * 16], acc, 256, wmma::mem_row_major);
    }
    __syncthreads();
    for (int e = threadIdx.x; e < 16 * 256; e += 256)
        sh[e / 256][e % 256] = tanhf(sh[e / 256][e % 256] + mlpb[e % 256]);
    __syncthreads();

    // GEMM2: 16x48, K=256
    if (warp < 3) {
        FragC acc;
        wmma::fill_fragment(acc, 0.0f);
        kloop3(acc, &sh[0][0], 256, adw + (size_t)(warp * 16) * 256, 256, 256);
        wmma::store_matrix_sync(&so[0][warp * 16], acc, 48, wmma::mem_row_major);
    }
    __syncthreads();
    for (int e = threadIdx.x; e < 16 * 48; e += 256)
        out[m0 * 48 + e] = so[e / 48][e % 48] + adb[e % 48];
}

// ---------------- host -------------------------------------------------------
extern "C" void kernel_launch(void* const* d_in, const int* in_sizes, int n_in,
                              void* d_out, int out_size) {
    const float* X     = (const float*)d_in[0];
    const float* Wih00 = (const float*)d_in[1];
    const float* Whh00 = (const float*)d_in[2];
    const float* bih00 = (const float*)d_in[3];
    const float* bhh00 = (const float*)d_in[4];
    const float* Wih01 = (const float*)d_in[5];
    const float* Whh01 = (const float*)d_in[6];
    const float* bih01 = (const float*)d_in[7];
    const float* bhh01 = (const float*)d_in[8];
    const float* Wih10 = (const float*)d_in[9];
    const float* Whh10 = (const float*)d_in[10];
    const float* bih10 = (const float*)d_in[11];
    const float* bhh10 = (const float*)d_in[12];
    const float* Wih11 = (const float*)d_in[13];
    const float* Whh11 = (const float*)d_in[14];
    const float* bih11 = (const float*)d_in[15];
    const float* bhh11 = (const float*)d_in[16];
    const float* mlpw  = (const float*)d_in[17];
    const float* mlpb  = (const float*)d_in[18];
    const float* adw   = (const float*)d_in[19];
    const float* adb   = (const float*)d_in[20];
    float* out = (float*)d_out;

    float *Xp, *Wih0p, *biasp, *Yb;
    cudaGetSymbolAddress((void**)&Xp, g_Xp);
    cudaGetSymbolAddress((void**)&Wih0p, g_Wih0);
    cudaGetSymbolAddress((void**)&biasp, g_bias);
    cudaGetSymbolAddress((void**)&Yb, g_Ybuf);
    float* Y0 = Yb;
    float* Y1 = Yb + (size_t)NRW * HD;
    float* Y2 = Yb + 2 * (size_t)NRW * HD;

    k_prep<<<512, 256>>>(X, Wih00, bih00, bhh00, bih01, bhh01,
                         bih10, bhh10, bih11, bhh11);

    // L00: rate 1 -> 256 steps, batch 256, K=32 (padded)
    lstm_k<256, 256, 32, 16, 32, 1><<<128, 256>>>(Xp, Wih0p, Whh00, biasp + 0 * 1024, Y0);
    // L01: rate 2 -> 128 steps, batch 512
    lstm_k<128, 512, 256, 32, 32, 1><<<128, 256>>>(Y0, Wih01, Whh01, biasp + 1 * 1024, Y1);
    // L10: rate 4 -> 64 steps, batch 1024
    lstm_k<64, 1024, 256, 32, 64, 1><<<128, 256>>>(Y1, Wih10, Whh10, biasp + 2 * 1024, Y0);
    // L11: rate 8 -> 32 steps, batch 2048
    lstm_k<32, 2048, 256, 32, 64, 2><<<128, 256>>>(Y0, Wih11, Whh11, biasp + 3 * 1024, Y2);

    // head: (Y2 + Y1) -> mlp tanh -> adapter
    head_k<<<NRW / 16, 256>>>(Y2, Y1, mlpw, mlpb, adw, adb, out);
}

// round 4
// speedup vs baseline: 1.3250x; 1.3250x over previous
#include <cuda_runtime.h>
#include <mma.h>

using namespace nvcuda;

#define NRW 65536
#define HD  256

// ---------------- static device buffers --------------------------------------
__device__ __align__(256) float g_Xp[NRW * 32];            // padded input (cols 20..31 = 0)
__device__ __align__(256) float g_Wih0[1024 * 32];         // padded W_ih_00
__device__ __align__(256) float g_bias[4][1024];           // b_ih + b_hh per layer
__device__ __align__(256) float g_G[(size_t)NRW * 1024];   // per-layer input preactivations
__device__ __align__(256) float g_Ybuf[3][(size_t)NRW * HD];
__device__ unsigned g_rdy[32];                             // per-row-group ready counters

typedef wmma::fragment<wmma::matrix_a, 16, 16, 8, wmma::precision::tf32, wmma::row_major> FragA;
typedef wmma::fragment<wmma::matrix_b, 16, 16, 8, wmma::precision::tf32, wmma::col_major> FragB;
typedef wmma::fragment<wmma::accumulator, 16, 16, 8, float> FragC;

__device__ __forceinline__ float sigf(float x) { return 1.0f / (1.0f + __expf(-x)); }

__device__ __forceinline__ void splitA(FragA& h, FragA& l) {
#pragma unroll
    for (int i = 0; i < h.num_elements; i++) {
        float v = h.x[i];
        float hh = wmma::__float_to_tf32(v);
        l.x[i] = wmma::__float_to_tf32(v - hh);
        h.x[i] = hh;
    }
}
__device__ __forceinline__ void splitB(FragB& h, FragB& l) {
#pragma unroll
    for (int i = 0; i < h.num_elements; i++) {
        float v = h.x[i];
        float hh = wmma::__float_to_tf32(v);
        l.x[i] = wmma::__float_to_tf32(v - hh);
        h.x[i] = hh;
    }
}

// 3xTF32 K-loop used by the head kernel
__device__ __forceinline__ void kloop3(FragC& acc, const float* __restrict__ A, int lda,
                                       const float* __restrict__ B, int ldb, int K) {
    for (int k = 0; k < K; k += 8) {
        FragA ah, al;
        FragB bh, bl;
        wmma::load_matrix_sync(ah, A + k, lda);
        wmma::load_matrix_sync(bh, B + k, ldb);
        splitA(ah, al);
        splitB(bh, bl);
        wmma::mma_sync(acc, ah, bh, acc);
        wmma::mma_sync(acc, ah, bl, acc);
        wmma::mma_sync(acc, al, bh, acc);
    }
}

// ---------------- prep: pad X / W_ih_00, combine biases ----------------------
__global__ void k_prep(const float* __restrict__ x, const float* __restrict__ wih0,
                       const float* __restrict__ bi0, const float* __restrict__ bh0,
                       const float* __restrict__ bi1, const float* __restrict__ bh1,
                       const float* __restrict__ bi2, const float* __restrict__ bh2,
                       const float* __restrict__ bi3, const float* __restrict__ bh3) {
    int tid = blockIdx.x * blockDim.x + threadIdx.x;
    int nt = gridDim.x * blockDim.x;
    for (int i = tid; i < NRW * 20; i += nt)
        g_Xp[(size_t)(i / 20) * 32 + (i % 20)] = x[i];
    for (int i = tid; i < 1024 * 20; i += nt)
        g_Wih0[(i / 20) * 32 + (i % 20)] = wih0[i];
    for (int i = tid; i < 1024; i += nt) {
        g_bias[0][i] = bi0[i] + bh0[i];
        g_bias[1][i] = bi1[i] + bh1[i];
        g_bias[2][i] = bi2[i] + bh2[i];
        g_bias[3][i] = bi3[i] + bh3[i];
    }
}

// ---------------- bulk input projection: G = X @ W^T (no bias) ---------------
// grid: (1024/128, NRW/128), block 256. BM=BN=128, BK=32, warp layout 4x2.
template <int K>
__global__ void __launch_bounds__(256, 1)
bulk_k(const float* __restrict__ X, const float* __restrict__ W, float* __restrict__ G) {
    __shared__ float sA[128 * 40];
    __shared__ float sB[128 * 40];
    const int n0 = blockIdx.x * 128;
    const size_t m0 = (size_t)blockIdx.y * 128;
    const int w = threadIdx.x >> 5;
    const int wr = (w >> 1) * 32;   // 4 row groups
    const int wc = (w & 1) * 64;    // 2 col groups

    FragC acc[2][4];
#pragma unroll
    for (int a = 0; a < 2; a++)
#pragma unroll
        for (int b = 0; b < 4; b++) wmma::fill_fragment(acc[a][b], 0.0f);

    for (int k0 = 0; k0 < K; k0 += 32) {
        __syncthreads();
        for (int i = threadIdx.x; i < 128 * 32; i += 256) {
            int r = i >> 5, ci = i & 31;
            sA[r * 40 + ci] = X[(m0 + r) * K + k0 + ci];
            sB[r * 40 + ci] = W[(size_t)(n0 + r) * K + k0 + ci];
        }
        __syncthreads();
#pragma unroll
        for (int kk = 0; kk < 32; kk += 8) {
            FragA ah[2], al[2];
#pragma unroll
            for (int a = 0; a < 2; a++) {
                wmma::load_matrix_sync(ah[a], &sA[(wr + a * 16) * 40 + kk], 40);
                splitA(ah[a], al[a]);
            }
#pragma unroll
            for (int b = 0; b < 4; b++) {
                FragB bh, bl;
                wmma::load_matrix_sync(bh, &sB[(wc + b * 16) * 40 + kk], 40);
                splitB(bh, bl);
#pragma unroll
                for (int a = 0; a < 2; a++) {
                    wmma::mma_sync(acc[a][b], ah[a], bh, acc[a][b]);
                    wmma::mma_sync(acc[a][b], ah[a], bl, acc[a][b]);
                    wmma::mma_sync(acc[a][b], al[a], bh, acc[a][b]);
                }
            }
        }
    }
#pragma unroll
    for (int a = 0; a < 2; a++)
#pragma unroll
        for (int b = 0; b < 4; b++)
            wmma::store_matrix_sync(G + (m0 + wr + a * 16) * 1024 + n0 + wc + b * 16,
                                    acc[a][b], 1024, wmma::mem_row_major);
}

// ---------------- persistent sequential LSTM (h-recurrence only) -------------
// Block tile: TM rows x TH hidden units (TN = 4*TH gate cols). 128 blocks.
// Row group rm syncs only with its C = 256/TH column-group peers.
template <int STEPS, int BEFF, int TM, int TH, int WM, int WN>
__global__ void __launch_bounds__(256, 1)
seq_k(const float* __restrict__ Whh, const float* __restrict__ G,
      const float* __restrict__ bias, float* __restrict__ Y,
      unsigned* __restrict__ rdy) {
    constexpr int TN = 4 * TH;
    constexpr int C = 256 / TH;
    constexpr int MA = TM / WM / 16;
    constexpr int NB = TN / WN / 16;
    constexpr int CPT = TM * TH / 256;
    extern __shared__ float sg[];   // [TM][TN], gate-major cols (g*TH + h)

    const int rm = blockIdx.x / C;
    const int cg = blockIdx.x % C;
    const int m0 = rm * TM;
    const int j0 = cg * TH;
    const int w = threadIdx.x >> 5;
    const int wr = (w / WN) * (TM / WM);
    const int wc = (w % WN) * (TN / WN);

    float cst[CPT];
#pragma unroll
    for (int q = 0; q < CPT; q++) cst[q] = 0.0f;

    for (int t = 0; t < STEPS; t++) {
        const size_t row0 = (size_t)t * BEFF + m0;
        if (t) {
            if (threadIdx.x == 0) {
                const unsigned tgt = (unsigned)C * (unsigned)t;
                while (*(volatile unsigned*)(rdy + rm) < tgt) __nanosleep(20);
                __threadfence();
            }
            __syncthreads();

            FragC acc[MA][NB];
#pragma unroll
            for (int a = 0; a < MA; a++)
#pragma unroll
                for (int b = 0; b < NB; b++) wmma::fill_fragment(acc[a][b], 0.0f);

            const float* Ab = Y + (row0 - BEFF) * HD;   // h_{t-1}, same rows
            for (int k0 = 0; k0 < HD; k0 += 8) {
                FragA ah[MA], al[MA];
#pragma unroll
                for (int a = 0; a < MA; a++) {
                    wmma::load_matrix_sync(ah[a], Ab + (size_t)(wr + a * 16) * HD + k0, HD);
                    splitA(ah[a], al[a]);
                }
#pragma unroll
                for (int b = 0; b < NB; b++) {
                    const int ncol = wc + b * 16;
                    const int gate = ncol / TH;
                    const int hoff = ncol % TH;
                    FragB bh, bl;
                    wmma::load_matrix_sync(bh,
                        Whh + (size_t)(gate * 256 + j0 + hoff) * HD + k0, HD);
                    splitB(bh, bl);
#pragma unroll
                    for (int a = 0; a < MA; a++) {
                        wmma::mma_sync(acc[a][b], ah[a], bh, acc[a][b]);
                        wmma::mma_sync(acc[a][b], ah[a], bl, acc[a][b]);
                        wmma::mma_sync(acc[a][b], al[a], bh, acc[a][b]);
                    }
                }
            }
#pragma unroll
            for (int a = 0; a < MA; a++)
#pragma unroll
                for (int b = 0; b < NB; b++)
                    wmma::store_matrix_sync(sg + (wr + a * 16) * TN + (wc + b * 16),
                                            acc[a][b], TN, wmma::mem_row_major);
            __syncthreads();
        }

        // ---- elementwise; c in registers ----
#pragma unroll
        for (int q = 0; q < CPT; q++) {
            const int e = threadIdx.x + q * 256;
            const int r = e / TH;
            const int h = e % TH;
            const size_t grow = (row0 + r) * 1024;
            float pi = G[grow + 0 * 256 + j0 + h] + bias[0 * 256 + j0 + h];
            float pf = G[grow + 1 * 256 + j0 + h] + bias[1 * 256 + j0 + h];
            float pg = G[grow + 2 * 256 + j0 + h] + bias[2 * 256 + j0 + h];
            float po = G[grow + 3 * 256 + j0 + h] + bias[3 * 256 + j0 + h];
            if (t) {
                pi += sg[r * TN + 0 * TH + h];
                pf += sg[r * TN + 1 * TH + h];
                pg += sg[r * TN + 2 * TH + h];
                po += sg[r * TN + 3 * TH + h];
            }
            const float cn = sigf(pf) * cst[q] + sigf(pi) * tanhf(pg);
            cst[q] = cn;
            Y[(row0 + r) * HD + j0 + h] = sigf(po) * tanhf(cn);
        }
        __syncthreads();
        if (threadIdx.x == 0) {
            __threadfence();
            atomicAdd(rdy + rm, 1u);
        }
    }
    // reset counter for next launch (safe: nobody waits past C*(STEPS-1))
    if (cg == 0 && threadIdx.x == 0) {
        const unsigned fin = (unsigned)C * (unsigned)STEPS;
        while (*(volatile unsigned*)(rdy + rm) < fin) __nanosleep(20);
        *(volatile unsigned*)(rdy + rm) = 0u;
        __threadfence();
    }
}

// ---------------- head: out = tanh((Y2+Y1) @ mlp_w^T + b) @ ad_w^T + ad_b ----
__global__ void __launch_bounds__(256, 2)
head_k(const float* __restrict__ Y2, const float* __restrict__ Y1,
       const float* __restrict__ mlpw, const float* __restrict__ mlpb,
       const float* __restrict__ adw, const float* __restrict__ adb,
       float* __restrict__ out) {
    __shared__ float sx[16][256];
    __shared__ float sh[16][256];
    __shared__ float so[16][48];

    const int warp = threadIdx.x >> 5;
    const size_t m0 = (size_t)blockIdx.x * 16;

    for (int e = threadIdx.x; e < 16 * 256; e += 256) {
        const size_t gi = m0 * 256 + e;
        sx[e / 256][e % 256] = Y2[gi] + Y1[gi];
    }
    __syncthreads();

    for (int st = warp; st < 16; st += 8) {
        FragC acc;
        wmma::fill_fragment(acc, 0.0f);
        kloop3(acc, &sx[0][0], 256, mlpw + (size_t)(st * 16) * 256, 256, 256);
        wmma::store_matrix_sync(&sh[0][st * 16], acc, 256, wmma::mem_row_major);
    }
    __syncthreads();
    for (int e = threadIdx.x; e < 16 * 256; e += 256)
        sh[e / 256][e % 256] = tanhf(sh[e / 256][e % 256] + mlpb[e % 256]);
    __syncthreads();

    if (warp < 3) {
        FragC acc;
        wmma::fill_fragment(acc, 0.0f);
        kloop3(acc, &sh[0][0], 256, adw + (size_t)(warp * 16) * 256, 256, 256);
        wmma::store_matrix_sync(&so[0][warp * 16], acc, 48, wmma::mem_row_major);
    }
    __syncthreads();
    for (int e = threadIdx.x; e < 16 * 48; e += 256)
        out[m0 * 48 + e] = so[e / 48][e % 48] + adb[e % 48];
}

// ---------------- host -------------------------------------------------------
extern "C" void kernel_launch(void* const* d_in, const int* in_sizes, int n_in,
                              void* d_out, int out_size) {
    const float* X     = (const float*)d_in[0];
    const float* Wih00 = (const float*)d_in[1];
    const float* Whh00 = (const float*)d_in[2];
    const float* bih00 = (const float*)d_in[3];
    const float* bhh00 = (const float*)d_in[4];
    const float* Wih01 = (const float*)d_in[5];
    const float* Whh01 = (const float*)d_in[6];
    const float* bih01 = (const float*)d_in[7];
    const float* bhh01 = (const float*)d_in[8];
    const float* Wih10 = (const float*)d_in[9];
    const float* Whh10 = (const float*)d_in[10];
    const float* bih10 = (const float*)d_in[11];
    const float* bhh10 = (const float*)d_in[12];
    const float* Wih11 = (const float*)d_in[13];
    const float* Whh11 = (const float*)d_in[14];
    const float* bih11 = (const float*)d_in[15];
    const float* bhh11 = (const float*)d_in[16];
    const float* mlpw  = (const float*)d_in[17];
    const float* mlpb  = (const float*)d_in[18];
    const float* adw   = (const float*)d_in[19];
    const float* adb   = (const float*)d_in[20];
    float* out = (float*)d_out;

    float *Xp, *Wih0p, *biasp, *Gp, *Yb;
    unsigned* rdyp;
    cudaGetSymbolAddress((void**)&Xp, g_Xp);
    cudaGetSymbolAddress((void**)&Wih0p, g_Wih0);
    cudaGetSymbolAddress((void**)&biasp, g_bias);
    cudaGetSymbolAddress((void**)&Gp, g_G);
    cudaGetSymbolAddress((void**)&Yb, g_Ybuf);
    cudaGetSymbolAddress((void**)&rdyp, g_rdy);
    float* Y0 = Yb;
    float* Y1 = Yb + (size_t)NRW * HD;
    float* Y2 = Yb + 2 * (size_t)NRW * HD;

    // allow >48KB dynamic smem for the largest seq tile
    cudaFuncSetAttribute((const void*)seq_k<256, 256, 16, 32, 1, 8>,
                         cudaFuncAttributeMaxDynamicSharedMemorySize, 16 * 128 * 4);
    cudaFuncSetAttribute((const void*)seq_k<128, 512, 32, 32, 2, 4>,
                         cudaFuncAttributeMaxDynamicSharedMemorySize, 32 * 128 * 4);
    cudaFuncSetAttribute((const void*)seq_k<64, 1024, 32, 64, 2, 4>,
                         cudaFuncAttributeMaxDynamicSharedMemorySize, 32 * 256 * 4);
    cudaFuncSetAttribute((const void*)seq_k<32, 2048, 64, 64, 2, 4>,
                         cudaFuncAttributeMaxDynamicSharedMemorySize, 64 * 256 * 4);

    k_prep<<<512, 256>>>(X, Wih00, bih00, bhh00, bih01, bhh01,
                         bih10, bhh10, bih11, bhh11);

    dim3 bgrid(1024 / 128, NRW / 128);

    // ---- group 0 ----
    bulk_k<32><<<bgrid, 256>>>(Xp, Wih0p, Gp);
    seq_k<256, 256, 16, 32, 1, 8><<<128, 256, 16 * 128 * 4>>>(
        Whh00, Gp, biasp + 0 * 1024, Y0, rdyp);

    bulk_k<256><<<bgrid, 256>>>(Y0, Wih01, Gp);
    seq_k<128, 512, 32, 32, 2, 4><<<128, 256, 32 * 128 * 4>>>(
        Whh01, Gp, biasp + 1 * 1024, Y1, rdyp);

    // ---- group 1 ----
    bulk_k<256><<<bgrid, 256>>>(Y1, Wih10, Gp);
    seq_k<64, 1024, 32, 64, 2, 4><<<128, 256, 32 * 256 * 4>>>(
        Whh10, Gp, biasp + 2 * 1024, Y0, rdyp);

    bulk_k<256><<<bgrid, 256>>>(Y0, Wih11, Gp);
    seq_k<32, 2048, 64, 64, 2, 4><<<128, 256, 64 * 256 * 4>>>(
        Whh11, Gp, biasp + 3 * 1024, Y2, rdyp);

    // head: (Y2 + Y1) -> tanh(mlp) -> adapter
    head_k<<<NRW / 16, 256>>>(Y2, Y1, mlpw, mlpb, adw, adb, out);
}